// round 1
// baseline (speedup 1.0000x reference)
#include <cuda_runtime.h>
#include <math.h>

#define BATCH  32768
#define EMB    256
#define ADIM   64
#define NHEADS 2
#define KNEI   16

// ---------------- scratch (device globals; no allocation allowed) ----------------
__device__ float g_q  [BATCH * 128];            // [B, H*A]   16 MB
__device__ float g_qk [BATCH * 512];            // [B, H*D]   64 MB
__device__ float g_ctx[BATCH * 512];            // [B, H*D]   64 MB
__device__ float g_wkT[NHEADS * EMB * ADIM];    // [H, D, A]  128 KB
__device__ int   g_valid[BATCH];
__device__ int   g_maskflag;                    // 1 => mask is byte-packed bool, 0 => int32

// ---------------- mask dtype detection + expansion ----------------
__global__ void detect_mask_kernel(const unsigned int* __restrict__ m) {
    __shared__ int s;
    if (threadIdx.x == 0) s = 0;
    __syncthreads();
    int found = 0;
    // 2048 words = 8 KB, safely within either layout (bool: 32 KB, int32: 128 KB)
    for (int i = threadIdx.x; i < 2048; i += blockDim.x)
        if (m[i] > 1u) found = 1;
    if (found) s = 1;
    __syncthreads();
    if (threadIdx.x == 0) g_maskflag = s;
}

__global__ void expand_mask_kernel(const void* __restrict__ m) {
    int i = blockIdx.x * blockDim.x + threadIdx.x;
    if (i >= BATCH) return;
    int v;
    if (g_maskflag) v = (((const unsigned char*)m)[i] != 0);
    else            v = (((const int*)m)[i] != 0);
    g_valid[i] = v;
}

// ---------------- W_k transpose: [H,A,D] -> [H,D,A] so every GEMM is NT ----------------
__global__ void transpose_wk_kernel(const float* __restrict__ wk) {
    int idx = blockIdx.x * blockDim.x + threadIdx.x;
    if (idx >= NHEADS * ADIM * EMB) return;
    int h = idx / (ADIM * EMB);
    int r = idx - h * (ADIM * EMB);
    int a = r / EMB;
    int d = r - a * EMB;
    g_wkT[h * EMB * ADIM + d * ADIM + a] = wk[idx];
}

// ---------------- fp32 NT GEMM: C[m,n] = sum_k A[m,k] * Bw[n,k] (+bias) ----------------
// 128x64 tile, BK=16, 256 threads, 8x4 per thread.
#define GBM 128
#define GBN 64
#define GBK 16

__global__ __launch_bounds__(256) void gemm_nt_kernel(
    const float* __restrict__ A, int lda,
    const float* __restrict__ Bw, int ldb,
    float* __restrict__ C, int ldc,
    int Kdim,
    const float* __restrict__ bias,
    const int* __restrict__ valid)
{
    __shared__ float As[GBK][GBM];
    __shared__ float Bs[GBK][GBN];
    const int t  = threadIdx.x;
    const int m0 = blockIdx.y * GBM;
    const int n0 = blockIdx.x * GBN;
    const int lr = t >> 2;            // 0..63
    const int lc = (t & 3) * 4;       // 0,4,8,12
    const int tx = t & 15;            // n-tile 0..15 (4 cols each)
    const int ty = t >> 4;            // m-tile 0..15 (8 rows each)

    const float* Ap0 = A  + (long)(m0 + lr)      * lda + lc;
    const float* Ap1 = A  + (long)(m0 + lr + 64) * lda + lc;
    const float* Bp  = Bw + (long)(n0 + lr)      * ldb + lc;

    float acc[8][4];
    #pragma unroll
    for (int i = 0; i < 8; i++)
        #pragma unroll
        for (int j = 0; j < 4; j++) acc[i][j] = 0.f;

    for (int k0 = 0; k0 < Kdim; k0 += GBK) {
        float4 a0 = *reinterpret_cast<const float4*>(Ap0 + k0);
        float4 a1 = *reinterpret_cast<const float4*>(Ap1 + k0);
        float4 bv = *reinterpret_cast<const float4*>(Bp  + k0);
        As[lc + 0][lr]      = a0.x; As[lc + 1][lr]      = a0.y;
        As[lc + 2][lr]      = a0.z; As[lc + 3][lr]      = a0.w;
        As[lc + 0][lr + 64] = a1.x; As[lc + 1][lr + 64] = a1.y;
        As[lc + 2][lr + 64] = a1.z; As[lc + 3][lr + 64] = a1.w;
        Bs[lc + 0][lr] = bv.x; Bs[lc + 1][lr] = bv.y;
        Bs[lc + 2][lr] = bv.z; Bs[lc + 3][lr] = bv.w;
        __syncthreads();
        #pragma unroll
        for (int kk = 0; kk < GBK; ++kk) {
            float4 af0 = *reinterpret_cast<const float4*>(&As[kk][ty * 8]);
            float4 af1 = *reinterpret_cast<const float4*>(&As[kk][ty * 8 + 4]);
            float4 bf  = *reinterpret_cast<const float4*>(&Bs[kk][tx * 4]);
            float av[8] = {af0.x, af0.y, af0.z, af0.w, af1.x, af1.y, af1.z, af1.w};
            float bb[4] = {bf.x, bf.y, bf.z, bf.w};
            #pragma unroll
            for (int i = 0; i < 8; i++)
                #pragma unroll
                for (int j = 0; j < 4; j++)
                    acc[i][j] += av[i] * bb[j];
        }
        __syncthreads();
    }

    const int n = n0 + tx * 4;
    #pragma unroll
    for (int i = 0; i < 8; i++) {
        int m = m0 + ty * 8 + i;
        if (valid && !valid[m]) continue;   // masked rows: epilogue skipped (attn kernel wrote them)
        float4 r;
        r.x = acc[i][0]; r.y = acc[i][1]; r.z = acc[i][2]; r.w = acc[i][3];
        if (bias) { r.x += bias[n]; r.y += bias[n+1]; r.z += bias[n+2]; r.w += bias[n+3]; }
        *reinterpret_cast<float4*>(C + (long)m * ldc + n) = r;
    }
}

// ---------------- fused attention: scores -> softmax*w -> renorm -> ctx ----------------
// one block per row; invalid rows copy center->out and skip the 16 KB neigh read.
__global__ __launch_bounds__(128) void attn_kernel(
    const float* __restrict__ center,
    const float* __restrict__ neigh,
    const float* __restrict__ wts,
    const int*   __restrict__ valid,
    const float* __restrict__ qk,
    float* __restrict__ ctx,
    float* __restrict__ out)
{
    const int b = blockIdx.x;
    const int t = threadIdx.x;

    if (!valid[b]) {
        const float4* src = reinterpret_cast<const float4*>(center + (long)b * EMB);
        float4*       dst = reinterpret_cast<float4*>(out + (long)b * EMB);
        if (t < 64) dst[t] = src[t];
        return;
    }

    __shared__ float sn[KNEI * EMB];   // 16 KB neighbor tile
    __shared__ float sq[512];          // qk for both heads
    __shared__ float sscore[32];
    __shared__ float sattn[32];

    const float4* np = reinterpret_cast<const float4*>(neigh + (long)b * KNEI * EMB);
    float4* snp = reinterpret_cast<float4*>(sn);
    #pragma unroll
    for (int i = 0; i < 8; i++) snp[t + i * 128] = np[t + i * 128];
    reinterpret_cast<float4*>(sq)[t] =
        reinterpret_cast<const float4*>(qk + (long)b * 512)[t];
    __syncthreads();

    // scores: 32 (h,j) pairs x 4 threads each
    {
        const int g = t >> 2, sub = t & 3;
        const int h = g >> 4, j = g & 15;
        const float* qh = sq + h * EMB;
        const float* nj = sn + j * EMB;
        float p = 0.f;
        #pragma unroll 8
        for (int i = sub; i < EMB; i += 4) p += qh[i] * nj[i];
        p += __shfl_xor_sync(0xffffffffu, p, 1);
        p += __shfl_xor_sync(0xffffffffu, p, 2);
        if (sub == 0) sscore[g] = p * 0.125f;   // 1/sqrt(64)
    }
    __syncthreads();

    // softmax * weights, renormalize: warp w handles head w on lanes 0..15
    {
        const int wid = t >> 5, lane = t & 31;
        if (wid < NHEADS && lane < KNEI) {
            float s = sscore[wid * KNEI + lane];
            float m = s;
            #pragma unroll
            for (int o = 8; o > 0; o >>= 1) m = fmaxf(m, __shfl_xor_sync(0xffffu, m, o));
            float e = expf(s - m);
            float se = e;
            #pragma unroll
            for (int o = 8; o > 0; o >>= 1) se += __shfl_xor_sync(0xffffu, se, o);
            float a = (e / se) * wts[b * KNEI + lane];
            float sa = a;
            #pragma unroll
            for (int o = 8; o > 0; o >>= 1) sa += __shfl_xor_sync(0xffffu, sa, o);
            sattn[wid * KNEI + lane] = a / (sa + 1e-8f);
        }
    }
    __syncthreads();

    // ctx[h,d] = sum_j attn[h,j] * neigh[j,d]
    float* cptr = ctx + (long)b * 512;
    #pragma unroll
    for (int r = 0; r < 4; r++) {
        const int idx = r * 128 + t;          // 0..511
        const int d = idx & 255, h = idx >> 8;
        float acc = 0.f;
        #pragma unroll
        for (int j = 0; j < KNEI; j++) acc += sattn[h * KNEI + j] * sn[j * EMB + d];
        cptr[idx] = acc;
    }
}

// ---------------- launch ----------------
extern "C" void kernel_launch(void* const* d_in, const int* in_sizes, int n_in,
                              void* d_out, int out_size)
{
    const float* center = (const float*)d_in[0];
    const float* neigh  = (const float*)d_in[1];
    const float* wts    = (const float*)d_in[2];
    const void*  mask   = d_in[3];
    const float* Wq     = (const float*)d_in[4];   // [H,A,D] = [128,256]
    const float* Wk     = (const float*)d_in[5];   // [H,A,D]
    const float* Wout   = (const float*)d_in[6];   // [256,512]
    const float* bout   = (const float*)d_in[7];
    float* out = (float*)d_out;

    float *gq, *gqk, *gctx, *gwkT;
    int *gvalid;
    cudaGetSymbolAddress((void**)&gq,    g_q);
    cudaGetSymbolAddress((void**)&gqk,   g_qk);
    cudaGetSymbolAddress((void**)&gctx,  g_ctx);
    cudaGetSymbolAddress((void**)&gwkT,  g_wkT);
    cudaGetSymbolAddress((void**)&gvalid, g_valid);

    detect_mask_kernel<<<1, 256>>>((const unsigned int*)mask);
    expand_mask_kernel<<<BATCH / 256, 256>>>(mask);
    transpose_wk_kernel<<<(NHEADS * ADIM * EMB + 255) / 256, 256>>>(Wk);

    // q = center @ Wq^T : [B,128], K=256
    {
        dim3 grid(128 / GBN, BATCH / GBM);
        gemm_nt_kernel<<<grid, 256>>>(center, EMB, Wq, EMB, gq, 128, EMB, nullptr, nullptr);
    }
    // qk[h] = q[h] @ WkT[h]^T : [B,256], K=64, per head
    {
        dim3 grid(EMB / GBN, BATCH / GBM);
        gemm_nt_kernel<<<grid, 256>>>(gq,      128, gwkT,               ADIM, gqk,       512, ADIM, nullptr, nullptr);
        gemm_nt_kernel<<<grid, 256>>>(gq + 64, 128, gwkT + EMB * ADIM,  ADIM, gqk + 256, 512, ADIM, nullptr, nullptr);
    }
    // fused attention (also copies center->out on masked rows)
    attn_kernel<<<BATCH, 128>>>(center, neigh, wts, gvalid, gqk, gctx, out);
    // out = ctx @ Wout^T + b : [B,256], K=512 (valid rows only)
    {
        dim3 grid(EMB / GBN, BATCH / GBM);
        gemm_nt_kernel<<<grid, 256>>>(gctx, 512, Wout, 512, out, EMB, 512, bout, gvalid);
    }
}

// round 2
// speedup vs baseline: 1.2859x; 1.2859x over previous
#include <cuda_runtime.h>
#include <math.h>

#define BATCH  32768
#define EMB    256
#define ADIM   64
#define NHEADS 2
#define KNEI   16

// ---------------- scratch (device globals; no allocation allowed) ----------------
__device__ float g_q  [BATCH * 128];            // [Bc, H*A]  compacted
__device__ float g_qk [BATCH * 512];            // [Bc, H*D]  compacted
__device__ float g_ctx[BATCH * 512];            // [Bc, H*D]  compacted
__device__ float g_wkT[NHEADS * EMB * ADIM];    // [H, D, A]
__device__ int   g_valid[BATCH];
__device__ int   g_perm [BATCH];                // compacted row index -> batch row
__device__ int   g_nvalid;
__device__ int   g_maskflag;

// ---------------- mask dtype detection + expansion ----------------
__global__ void detect_mask_kernel(const unsigned int* __restrict__ m) {
    __shared__ int s;
    if (threadIdx.x == 0) s = 0;
    __syncthreads();
    int found = 0;
    for (int i = threadIdx.x; i < 2048; i += blockDim.x)
        if (m[i] > 1u) found = 1;
    if (found) s = 1;
    __syncthreads();
    if (threadIdx.x == 0) g_maskflag = s;
}

__global__ void expand_mask_kernel(const void* __restrict__ m) {
    int i = blockIdx.x * blockDim.x + threadIdx.x;
    if (i >= BATCH) return;
    int v;
    if (g_maskflag) v = (((const unsigned char*)m)[i] != 0);
    else            v = (((const int*)m)[i] != 0);
    g_valid[i] = v;
}

// ---------------- ordered compaction: perm[0..nvalid) = valid rows ----------------
__global__ void compact_kernel() {
    __shared__ int s[1024];
    const int t = threadIdx.x;
    const int base = t * 32;
    int c = 0;
    #pragma unroll 4
    for (int i = 0; i < 32; i++) c += g_valid[base + i];
    s[t] = c;
    __syncthreads();
    // Hillis-Steele inclusive scan over 1024
    for (int off = 1; off < 1024; off <<= 1) {
        int v = (t >= off) ? s[t - off] : 0;
        __syncthreads();
        s[t] += v;
        __syncthreads();
    }
    const int total = s[1023];
    int o = s[t] - c;   // exclusive offset
    for (int i = 0; i < 32; i++)
        if (g_valid[base + i]) g_perm[o++] = base + i;
    // pad tail with row 0 so gathered loads past nvalid are safe
    for (int i = total + t; i < BATCH; i += 1024) g_perm[i] = 0;
    if (t == 0) g_nvalid = total;
}

// ---------------- W_k transpose: [H,A,D] -> [H,D,A] ----------------
__global__ void transpose_wk_kernel(const float* __restrict__ wk) {
    int idx = blockIdx.x * blockDim.x + threadIdx.x;
    if (idx >= NHEADS * ADIM * EMB) return;
    int h = idx / (ADIM * EMB);
    int r = idx - h * (ADIM * EMB);
    int a = r / EMB;
    int d = r - a * EMB;
    g_wkT[h * EMB * ADIM + d * ADIM + a] = wk[idx];
}

// ---------------- fp32 NT GEMM, 128x128 tile, TK=8, 8x8/thread, dbl-buffered ----
// C[m,n] = sum_k A[am,k] * B[n,k] (+bias), am = Aperm?perm:m, store to Cperm?perm:m.
// M bound is g_nvalid (all GEMMs run on compacted rows).
__global__ __launch_bounds__(256) void gemm_nt2(
    const float* __restrict__ A, int lda,
    const float* __restrict__ B, int ldb,
    float* __restrict__ C, int ldc,
    int Kdim,
    const float* __restrict__ bias,
    const int* __restrict__ Aperm,
    const int* __restrict__ Cperm)
{
    __shared__ float As[2][8][132];
    __shared__ float Bs[2][8][132];

    const int Mvalid = g_nvalid;
    const int m0 = blockIdx.y * 128;
    if (m0 >= Mvalid) return;
    const int n0 = blockIdx.x * 128;
    const int t  = threadIdx.x;
    const int lr = t >> 1;            // 0..127  (tile row for loading)
    const int lk = (t & 1) * 4;       // 0 or 4  (k offset for loading)
    const int tx = t & 15;            // 0..15   (8 cols each)
    const int ty = t >> 4;            // 0..15   (8 rows each)

    int arow = m0 + lr;
    if (Aperm) arow = Aperm[arow];
    const float* pa = A + (size_t)arow * lda + lk;
    const float* pb = B + (size_t)(n0 + lr) * ldb + lk;

    float acc[8][8];
    #pragma unroll
    for (int i = 0; i < 8; i++)
        #pragma unroll
        for (int j = 0; j < 8; j++) acc[i][j] = 0.f;

    float4 av = *reinterpret_cast<const float4*>(pa);
    float4 bv = *reinterpret_cast<const float4*>(pb);
    As[0][lk + 0][lr] = av.x; As[0][lk + 1][lr] = av.y;
    As[0][lk + 2][lr] = av.z; As[0][lk + 3][lr] = av.w;
    Bs[0][lk + 0][lr] = bv.x; Bs[0][lk + 1][lr] = bv.y;
    Bs[0][lk + 2][lr] = bv.z; Bs[0][lk + 3][lr] = bv.w;
    __syncthreads();

    int buf = 0;
    for (int k0 = 0; k0 < Kdim; k0 += 8) {
        const bool more = (k0 + 8 < Kdim);
        if (more) {
            av = *reinterpret_cast<const float4*>(pa + k0 + 8);
            bv = *reinterpret_cast<const float4*>(pb + k0 + 8);
        }
        #pragma unroll
        for (int kk = 0; kk < 8; ++kk) {
            float4 a0 = *reinterpret_cast<const float4*>(&As[buf][kk][ty * 8]);
            float4 a1 = *reinterpret_cast<const float4*>(&As[buf][kk][ty * 8 + 4]);
            float4 b0 = *reinterpret_cast<const float4*>(&Bs[buf][kk][tx * 8]);
            float4 b1 = *reinterpret_cast<const float4*>(&Bs[buf][kk][tx * 8 + 4]);
            float a[8] = {a0.x, a0.y, a0.z, a0.w, a1.x, a1.y, a1.z, a1.w};
            float b[8] = {b0.x, b0.y, b0.z, b0.w, b1.x, b1.y, b1.z, b1.w};
            #pragma unroll
            for (int i = 0; i < 8; i++)
                #pragma unroll
                for (int j = 0; j < 8; j++)
                    acc[i][j] += a[i] * b[j];
        }
        if (more) {
            int nb = buf ^ 1;
            As[nb][lk + 0][lr] = av.x; As[nb][lk + 1][lr] = av.y;
            As[nb][lk + 2][lr] = av.z; As[nb][lk + 3][lr] = av.w;
            Bs[nb][lk + 0][lr] = bv.x; Bs[nb][lk + 1][lr] = bv.y;
            Bs[nb][lk + 2][lr] = bv.z; Bs[nb][lk + 3][lr] = bv.w;
        }
        __syncthreads();
        buf ^= 1;
    }

    const int n = n0 + tx * 8;
    float4 bia0 = {0.f, 0.f, 0.f, 0.f}, bia1 = {0.f, 0.f, 0.f, 0.f};
    if (bias) {
        bia0 = *reinterpret_cast<const float4*>(bias + n);
        bia1 = *reinterpret_cast<const float4*>(bias + n + 4);
    }
    #pragma unroll
    for (int i = 0; i < 8; i++) {
        int gm = m0 + ty * 8 + i;
        if (gm >= Mvalid) continue;
        int crow = Cperm ? Cperm[gm] : gm;
        float* cp = C + (size_t)crow * ldc + n;
        float4 r0, r1;
        r0.x = acc[i][0] + bia0.x; r0.y = acc[i][1] + bia0.y;
        r0.z = acc[i][2] + bia0.z; r0.w = acc[i][3] + bia0.w;
        r1.x = acc[i][4] + bia1.x; r1.y = acc[i][5] + bia1.y;
        r1.z = acc[i][6] + bia1.z; r1.w = acc[i][7] + bia1.w;
        *reinterpret_cast<float4*>(cp)     = r0;
        *reinterpret_cast<float4*>(cp + 4) = r1;
    }
}

// ---------------- fused attention on compacted rows ----------------
__global__ __launch_bounds__(128) void attn_kernel(
    const float* __restrict__ neigh,
    const float* __restrict__ wts,
    const float* __restrict__ qk,
    float* __restrict__ ctx)
{
    const int i = blockIdx.x;
    if (i >= g_nvalid) return;
    const int b = g_perm[i];
    const int t = threadIdx.x;

    __shared__ float sn[KNEI * EMB];   // 16 KB neighbor tile
    __shared__ float sq[512];
    __shared__ float sscore[32];
    __shared__ float sattn[32];

    const float4* np = reinterpret_cast<const float4*>(neigh + (long)b * KNEI * EMB);
    float4* snp = reinterpret_cast<float4*>(sn);
    #pragma unroll
    for (int r = 0; r < 8; r++) snp[t + r * 128] = np[t + r * 128];
    reinterpret_cast<float4*>(sq)[t] =
        reinterpret_cast<const float4*>(qk + (long)i * 512)[t];
    __syncthreads();

    // scores: 32 (h,j) pairs x 4 threads each
    {
        const int g = t >> 2, sub = t & 3;
        const int h = g >> 4, j = g & 15;
        const float* qh = sq + h * EMB;
        const float* nj = sn + j * EMB;
        float p = 0.f;
        #pragma unroll 8
        for (int d = sub; d < EMB; d += 4) p += qh[d] * nj[d];
        p += __shfl_xor_sync(0xffffffffu, p, 1);
        p += __shfl_xor_sync(0xffffffffu, p, 2);
        if (sub == 0) sscore[g] = p * 0.125f;   // 1/sqrt(64)
    }
    __syncthreads();

    // softmax * weights, renormalize
    {
        const int wid = t >> 5, lane = t & 31;
        if (wid < NHEADS && lane < KNEI) {
            float s = sscore[wid * KNEI + lane];
            float m = s;
            #pragma unroll
            for (int o = 8; o > 0; o >>= 1) m = fmaxf(m, __shfl_xor_sync(0xffffu, m, o));
            float e = expf(s - m);
            float se = e;
            #pragma unroll
            for (int o = 8; o > 0; o >>= 1) se += __shfl_xor_sync(0xffffu, se, o);
            float a = (e / se) * wts[b * KNEI + lane];
            float sa = a;
            #pragma unroll
            for (int o = 8; o > 0; o >>= 1) sa += __shfl_xor_sync(0xffffu, sa, o);
            sattn[wid * KNEI + lane] = a / (sa + 1e-8f);
        }
    }
    __syncthreads();

    // ctx[h,d] = sum_j attn[h,j] * neigh[j,d]
    float* cptr = ctx + (long)i * 512;
    #pragma unroll
    for (int r = 0; r < 4; r++) {
        const int idx = r * 128 + t;
        const int d = idx & 255, h = idx >> 8;
        float acc2 = 0.f;
        #pragma unroll
        for (int j = 0; j < KNEI; j++) acc2 += sattn[h * KNEI + j] * sn[j * EMB + d];
        cptr[idx] = acc2;
    }
}

// ---------------- invalid rows: out = center ----------------
__global__ void copy_invalid_kernel(const float* __restrict__ center,
                                    float* __restrict__ out)
{
    int v = blockIdx.x * blockDim.x + threadIdx.x;   // over BATCH*64 float4
    int b = v >> 6;
    if (!g_valid[b])
        reinterpret_cast<float4*>(out)[v] =
            reinterpret_cast<const float4*>(center)[v];
}

// ---------------- launch ----------------
extern "C" void kernel_launch(void* const* d_in, const int* in_sizes, int n_in,
                              void* d_out, int out_size)
{
    const float* center = (const float*)d_in[0];
    const float* neigh  = (const float*)d_in[1];
    const float* wts    = (const float*)d_in[2];
    const void*  mask   = d_in[3];
    const float* Wq     = (const float*)d_in[4];   // [H*A, D] = [128,256]
    const float* Wk     = (const float*)d_in[5];
    const float* Wout   = (const float*)d_in[6];   // [256,512]
    const float* bout   = (const float*)d_in[7];
    float* out = (float*)d_out;

    float *gq, *gqk, *gctx, *gwkT;
    int *gperm;
    cudaGetSymbolAddress((void**)&gq,    g_q);
    cudaGetSymbolAddress((void**)&gqk,   g_qk);
    cudaGetSymbolAddress((void**)&gctx,  g_ctx);
    cudaGetSymbolAddress((void**)&gwkT,  g_wkT);
    cudaGetSymbolAddress((void**)&gperm, g_perm);

    detect_mask_kernel<<<1, 256>>>((const unsigned int*)mask);
    expand_mask_kernel<<<BATCH / 256, 256>>>(mask);
    compact_kernel<<<1, 1024>>>();
    transpose_wk_kernel<<<(NHEADS * ADIM * EMB + 255) / 256, 256>>>(Wk);

    // q = gather(center) @ Wq^T : [Bv,128], K=256
    {
        dim3 grid(1, BATCH / 128);
        gemm_nt2<<<grid, 256>>>(center, EMB, Wq, EMB, gq, 128, EMB,
                                nullptr, gperm, nullptr);
    }
    // qk[h] = q[:,h*64:] @ WkT[h]^T : [Bv,256], K=64 per head
    {
        dim3 grid(EMB / 128, BATCH / 128);
        gemm_nt2<<<grid, 256>>>(gq,      128, gwkT,              ADIM, gqk,       512, ADIM,
                                nullptr, nullptr, nullptr);
        gemm_nt2<<<grid, 256>>>(gq + 64, 128, gwkT + EMB * ADIM, ADIM, gqk + 256, 512, ADIM,
                                nullptr, nullptr, nullptr);
    }
    // fused attention on valid rows
    attn_kernel<<<BATCH, 128>>>(neigh, wts, gqk, gctx);
    // invalid rows: out = center
    copy_invalid_kernel<<<BATCH * 64 / 256, 256>>>(center, out);
    // out = ctx @ Wout^T + b, scattered to valid rows : [Bv,256], K=512
    {
        dim3 grid(EMB / 128, BATCH / 128);
        gemm_nt2<<<grid, 256>>>(gctx, 512, Wout, 512, out, EMB, 512,
                                bout, nullptr, gperm);
    }
}

// round 4
// speedup vs baseline: 1.4535x; 1.1304x over previous
#include <cuda_runtime.h>
#include <cuda_bf16.h>
#include <math.h>
#include <stdint.h>

#define BATCH  32768
#define EMB    256
#define ADIM   64
#define NHEADS 2
#define KNEI   16

// ---------------- scratch (device globals; no allocation allowed) ----------------
__device__ __nv_bfloat16 g_ch [BATCH * EMB];     // center gathered, bf16 hi
__device__ __nv_bfloat16 g_cl [BATCH * EMB];     // center gathered, bf16 lo
__device__ __nv_bfloat16 g_qh [BATCH * 128];     // q hi
__device__ __nv_bfloat16 g_ql [BATCH * 128];     // q lo
__device__ float         g_qk [BATCH * 512];     // qk fp32 (compacted)
__device__ __nv_bfloat16 g_cxh[BATCH * 512];     // ctx hi
__device__ __nv_bfloat16 g_cxl[BATCH * 512];     // ctx lo
__device__ __nv_bfloat16 g_wqh[128 * 256], g_wql[128 * 256];
__device__ __nv_bfloat16 g_wkh[NHEADS * 256 * 64], g_wkl[NHEADS * 256 * 64];  // WkT [h][d][a]
__device__ __nv_bfloat16 g_woh[256 * 512], g_wol[256 * 512];
__device__ int g_valid[BATCH];
__device__ int g_perm [BATCH];
__device__ int g_nvalid;
__device__ int g_maskflag;

// ---------------- helpers ----------------
__device__ __forceinline__ uint32_t smem_u32(const void* p) {
    uint32_t a;
    asm("{ .reg .u64 t; cvta.to.shared.u64 t, %1; cvt.u32.u64 %0, t; }" : "=r"(a) : "l"(p));
    return a;
}

#define LDSM4(r0, r1, r2, r3, addr) \
    asm volatile("ldmatrix.sync.aligned.m8n8.x4.shared.b16 {%0,%1,%2,%3}, [%4];" \
                 : "=r"(r0), "=r"(r1), "=r"(r2), "=r"(r3) : "r"(addr))

#define MMA16816(d, a, b0, b1) \
    asm volatile("mma.sync.aligned.m16n8k16.row.col.f32.bf16.bf16.f32 " \
                 "{%0,%1,%2,%3}, {%4,%5,%6,%7}, {%8,%9}, {%0,%1,%2,%3};" \
                 : "+f"((d)[0]), "+f"((d)[1]), "+f"((d)[2]), "+f"((d)[3]) \
                 : "r"((a)[0]), "r"((a)[1]), "r"((a)[2]), "r"((a)[3]), \
                   "r"(b0), "r"(b1))

// ---------------- mask dtype detection + expansion + compaction ----------------
__global__ void detect_mask_kernel(const unsigned int* __restrict__ m) {
    __shared__ int s;
    if (threadIdx.x == 0) s = 0;
    __syncthreads();
    int found = 0;
    for (int i = threadIdx.x; i < 2048; i += blockDim.x)
        if (m[i] > 1u) found = 1;
    if (found) s = 1;
    __syncthreads();
    if (threadIdx.x == 0) g_maskflag = s;
}

__global__ void expand_mask_kernel(const void* __restrict__ m) {
    int i = blockIdx.x * blockDim.x + threadIdx.x;
    if (i >= BATCH) return;
    int v;
    if (g_maskflag) v = (((const unsigned char*)m)[i] != 0);
    else            v = (((const int*)m)[i] != 0);
    g_valid[i] = v;
}

__global__ void compact_kernel() {
    __shared__ int s[1024];
    const int t = threadIdx.x;
    const int base = t * 32;
    int c = 0;
    #pragma unroll 4
    for (int i = 0; i < 32; i++) c += g_valid[base + i];
    s[t] = c;
    __syncthreads();
    for (int off = 1; off < 1024; off <<= 1) {
        int v = (t >= off) ? s[t - off] : 0;
        __syncthreads();
        s[t] += v;
        __syncthreads();
    }
    const int total = s[1023];
    int o = s[t] - c;
    for (int i = 0; i < 32; i++)
        if (g_valid[base + i]) g_perm[o++] = base + i;
    for (int i = total + t; i < BATCH; i += 1024) g_perm[i] = 0;
    if (t == 0) g_nvalid = total;
}

// ---------------- bf16 hi/lo split preps ----------------
__device__ __forceinline__ void split1(float v, __nv_bfloat16* hi, __nv_bfloat16* lo) {
    __nv_bfloat16 h = __float2bfloat16(v);
    *hi = h;
    *lo = __float2bfloat16(v - __bfloat162float(h));
}

__global__ void split_kernel(const float* __restrict__ src,
                             __nv_bfloat16* __restrict__ hi,
                             __nv_bfloat16* __restrict__ lo, int n) {
    int i = blockIdx.x * blockDim.x + threadIdx.x;
    if (i >= n) return;
    split1(src[i], hi + i, lo + i);
}

__global__ void transpose_split_wk(const float* __restrict__ wk) {
    int idx = blockIdx.x * blockDim.x + threadIdx.x;
    if (idx >= NHEADS * ADIM * EMB) return;
    int h = idx / (ADIM * EMB);
    int r = idx - h * (ADIM * EMB);
    int a = r / EMB;
    int d = r - a * EMB;
    int o = h * EMB * ADIM + d * ADIM + a;
    split1(wk[idx], g_wkh + o, g_wkl + o);
}

__global__ void gather_split_center(const float* __restrict__ center) {
    int i = blockIdx.x * blockDim.x + threadIdx.x;   // over BATCH*EMB
    int row = i >> 8, d = i & 255;
    float v = center[(size_t)g_perm[row] * EMB + d];
    split1(v, g_ch + i, g_cl + i);
}

// ---------------- bf16x3 HMMA GEMM: C[m,n] = A[m,:]·B[n,:] ----------------
// Block 128x128, 8 warps (4x2), warp tile 32x64, BK=32.
// A = bf16 hi/lo (compacted rows); B = bf16 hi/lo weights [n][k].
// Output either fp32 (opt bias, opt row-scatter via Cperm) or bf16 hi/lo split.
__global__ __launch_bounds__(256) void gemm_mma(
    const __nv_bfloat16* __restrict__ Ahi, const __nv_bfloat16* __restrict__ Alo,
    int lda, int acol,
    const __nv_bfloat16* __restrict__ Bhi, const __nv_bfloat16* __restrict__ Blo,
    int ldb, int Kdim,
    float* __restrict__ Cf, int ldcf,
    __nv_bfloat16* __restrict__ Chi, __nv_bfloat16* __restrict__ Clo, int ldcb,
    const float* __restrict__ bias,
    const int* __restrict__ Cperm)
{
    __shared__ __align__(16) __nv_bfloat16 sA[2][128][40];   // [hi/lo][row][k] pad 40
    __shared__ __align__(16) __nv_bfloat16 sB[2][128][40];

    const int nvalid = g_nvalid;
    const int m0 = blockIdx.y * 128;
    if (m0 >= nvalid) return;
    const int n0 = blockIdx.x * 128;

    const int t    = threadIdx.x;
    const int wid  = t >> 5;
    const int lane = t & 31;
    const int wm   = wid >> 1;          // 0..3 -> m offset wm*32
    const int wn   = wid & 1;           // 0..1 -> n offset wn*64

    float c[2][8][4];
    #pragma unroll
    for (int mi = 0; mi < 2; mi++)
        #pragma unroll
        for (int nj = 0; nj < 8; nj++)
            #pragma unroll
            for (int r = 0; r < 4; r++) c[mi][nj][r] = 0.f;

    // ldmatrix per-lane offsets
    const int la = lane & 15, ga = lane >> 4;          // A: row+la, col+ga*8
    const int lb = lane & 7,  gb = lane >> 3;          // B: row+lb+(gb>>1)*8, col+(gb&1)*8
    const uint32_t baseAhi = smem_u32(&sA[0][0][0]);
    const uint32_t baseAlo = smem_u32(&sA[1][0][0]);
    const uint32_t baseBhi = smem_u32(&sB[0][0][0]);
    const uint32_t baseBlo = smem_u32(&sB[1][0][0]);
    const uint32_t aoff = (uint32_t)((wm * 32 + la) * 80 + ga * 16);
    const uint32_t boff = (uint32_t)((wn * 64 + lb + (gb >> 1) * 8) * 80 + (gb & 1) * 16);

    const int nStages = Kdim >> 5;
    for (int s = 0; s < nStages; s++) {
        const int kb = s * 32;
        // ---- global -> smem : 2048 uint4, 8 per thread ----
        #pragma unroll
        for (int i = 0; i < 8; i++) {
            int idx = i * 256 + t;
            int mat = idx >> 9;          // 0 Ahi, 1 Alo, 2 Bhi, 3 Blo
            int rem = idx & 511;
            int row = rem >> 2, c4 = rem & 3;
            uint4 v;
            if (mat == 0)
                v = *reinterpret_cast<const uint4*>(Ahi + (size_t)(m0 + row) * lda + acol + kb + c4 * 8);
            else if (mat == 1)
                v = *reinterpret_cast<const uint4*>(Alo + (size_t)(m0 + row) * lda + acol + kb + c4 * 8);
            else if (mat == 2)
                v = *reinterpret_cast<const uint4*>(Bhi + (size_t)(n0 + row) * ldb + kb + c4 * 8);
            else
                v = *reinterpret_cast<const uint4*>(Blo + (size_t)(n0 + row) * ldb + kb + c4 * 8);
            if (mat < 2) *reinterpret_cast<uint4*>(&sA[mat][row][c4 * 8]) = v;
            else         *reinterpret_cast<uint4*>(&sB[mat - 2][row][c4 * 8]) = v;
        }
        __syncthreads();

        #pragma unroll
        for (int kk = 0; kk < 2; kk++) {
            const uint32_t kby = kk * 32;   // 16 elems * 2B
            uint32_t ah[2][4], al[2][4];
            #pragma unroll
            for (int mi = 0; mi < 2; mi++) {
                uint32_t adr = aoff + (uint32_t)(mi * 16 * 80) + kby;
                LDSM4(ah[mi][0], ah[mi][1], ah[mi][2], ah[mi][3], baseAhi + adr);
                LDSM4(al[mi][0], al[mi][1], al[mi][2], al[mi][3], baseAlo + adr);
            }
            uint32_t bh[4][4], bl[4][4];
            #pragma unroll
            for (int nj = 0; nj < 4; nj++) {
                uint32_t adr = boff + (uint32_t)(nj * 16 * 80) + kby;
                LDSM4(bh[nj][0], bh[nj][1], bh[nj][2], bh[nj][3], baseBhi + adr);
                LDSM4(bl[nj][0], bl[nj][1], bl[nj][2], bl[nj][3], baseBlo + adr);
            }
            #pragma unroll
            for (int mi = 0; mi < 2; mi++)
                #pragma unroll
                for (int t8 = 0; t8 < 8; t8++) {
                    const int nj = t8 >> 1, sel = (t8 & 1) * 2;
                    MMA16816(c[mi][t8], ah[mi], bh[nj][sel], bh[nj][sel + 1]);
                    MMA16816(c[mi][t8], al[mi], bh[nj][sel], bh[nj][sel + 1]);
                    MMA16816(c[mi][t8], ah[mi], bl[nj][sel], bl[nj][sel + 1]);
                }
        }
        __syncthreads();
    }

    // ---- epilogue ----
    const int rit  = lane >> 2;          // 0..7
    const int colp = (lane & 3) * 2;
    #pragma unroll
    for (int mi = 0; mi < 2; mi++) {
        #pragma unroll
        for (int half = 0; half < 2; half++) {
            const int gm = m0 + wm * 32 + mi * 16 + half * 8 + rit;
            const bool storeOK = (Cperm == nullptr) || (gm < nvalid);
            if (!storeOK) continue;
            const int crow = Cperm ? Cperm[gm] : gm;
            #pragma unroll
            for (int t8 = 0; t8 < 8; t8++) {
                const int col = n0 + wn * 64 + t8 * 8 + colp;
                float v0 = c[mi][t8][half * 2 + 0];
                float v1 = c[mi][t8][half * 2 + 1];
                if (Cf) {
                    if (bias) { v0 += bias[col]; v1 += bias[col + 1]; }
                    *reinterpret_cast<float2*>(Cf + (size_t)crow * ldcf + col) =
                        make_float2(v0, v1);
                } else {
                    __nv_bfloat16 h0 = __float2bfloat16(v0);
                    __nv_bfloat16 h1 = __float2bfloat16(v1);
                    __nv_bfloat16 l0 = __float2bfloat16(v0 - __bfloat162float(h0));
                    __nv_bfloat16 l1 = __float2bfloat16(v1 - __bfloat162float(h1));
                    *reinterpret_cast<__nv_bfloat162*>(Chi + (size_t)gm * ldcb + col) =
                        __nv_bfloat162(h0, h1);
                    *reinterpret_cast<__nv_bfloat162*>(Clo + (size_t)gm * ldcb + col) =
                        __nv_bfloat162(l0, l1);
                }
            }
        }
    }
}

// ---------------- fused attention on compacted rows (ctx -> bf16 hi/lo) ----------------
__global__ __launch_bounds__(128) void attn_kernel(
    const float* __restrict__ neigh,
    const float* __restrict__ wts,
    const float* __restrict__ qk)
{
    const int i = blockIdx.x;
    if (i >= g_nvalid) return;
    const int b = g_perm[i];
    const int t = threadIdx.x;

    __shared__ float sn[KNEI * EMB];
    __shared__ float sq[512];
    __shared__ float sscore[32];
    __shared__ float sattn[32];

    const float4* np = reinterpret_cast<const float4*>(neigh + (long)b * KNEI * EMB);
    float4* snp = reinterpret_cast<float4*>(sn);
    #pragma unroll
    for (int r = 0; r < 8; r++) snp[t + r * 128] = np[t + r * 128];
    reinterpret_cast<float4*>(sq)[t] =
        reinterpret_cast<const float4*>(qk + (long)i * 512)[t];
    __syncthreads();

    {
        const int g = t >> 2, sub = t & 3;
        const int h = g >> 4, j = g & 15;
        const float* qh = sq + h * EMB;
        const float* nj = sn + j * EMB;
        float p = 0.f;
        #pragma unroll 8
        for (int d = sub; d < EMB; d += 4) p += qh[d] * nj[d];
        p += __shfl_xor_sync(0xffffffffu, p, 1);
        p += __shfl_xor_sync(0xffffffffu, p, 2);
        if (sub == 0) sscore[g] = p * 0.125f;
    }
    __syncthreads();

    {
        const int wid = t >> 5, lane = t & 31;
        if (wid < NHEADS && lane < KNEI) {
            float s = sscore[wid * KNEI + lane];
            float m = s;
            #pragma unroll
            for (int o = 8; o > 0; o >>= 1) m = fmaxf(m, __shfl_xor_sync(0xffffu, m, o));
            float e = expf(s - m);
            float se = e;
            #pragma unroll
            for (int o = 8; o > 0; o >>= 1) se += __shfl_xor_sync(0xffffu, se, o);
            float a = (e / se) * wts[b * KNEI + lane];
            float sa = a;
            #pragma unroll
            for (int o = 8; o > 0; o >>= 1) sa += __shfl_xor_sync(0xffffu, sa, o);
            sattn[wid * KNEI + lane] = a / (sa + 1e-8f);
        }
    }
    __syncthreads();

    #pragma unroll
    for (int r = 0; r < 4; r++) {
        const int idx = r * 128 + t;
        const int d = idx & 255, h = idx >> 8;
        float acc = 0.f;
        #pragma unroll
        for (int j = 0; j < KNEI; j++) acc += sattn[h * KNEI + j] * sn[j * EMB + d];
        __nv_bfloat16 hi = __float2bfloat16(acc);
        g_cxh[(size_t)i * 512 + idx] = hi;
        g_cxl[(size_t)i * 512 + idx] = __float2bfloat16(acc - __bfloat162float(hi));
    }
}

// ---------------- invalid rows: out = center ----------------
__global__ void copy_invalid_kernel(const float* __restrict__ center,
                                    float* __restrict__ out)
{
    int v = blockIdx.x * blockDim.x + threadIdx.x;
    int b = v >> 6;
    if (!g_valid[b])
        reinterpret_cast<float4*>(out)[v] =
            reinterpret_cast<const float4*>(center)[v];
}

// ---------------- launch ----------------
extern "C" void kernel_launch(void* const* d_in, const int* in_sizes, int n_in,
                              void* d_out, int out_size)
{
    const float* center = (const float*)d_in[0];
    const float* neigh  = (const float*)d_in[1];
    const float* wts    = (const float*)d_in[2];
    const void*  mask   = d_in[3];
    const float* Wq     = (const float*)d_in[4];   // [128, 256]
    const float* Wk     = (const float*)d_in[5];   // [2, 64, 256]
    const float* Wout   = (const float*)d_in[6];   // [256, 512]
    const float* bout   = (const float*)d_in[7];
    float* out = (float*)d_out;

    __nv_bfloat16 *ch, *cl, *qh, *ql, *cxh, *cxl, *wqh, *wql, *wkh, *wkl, *woh, *wol;
    float *gqk;
    int *gperm;
    cudaGetSymbolAddress((void**)&ch,  g_ch);  cudaGetSymbolAddress((void**)&cl,  g_cl);
    cudaGetSymbolAddress((void**)&qh,  g_qh);  cudaGetSymbolAddress((void**)&ql,  g_ql);
    cudaGetSymbolAddress((void**)&cxh, g_cxh); cudaGetSymbolAddress((void**)&cxl, g_cxl);
    cudaGetSymbolAddress((void**)&wqh, g_wqh); cudaGetSymbolAddress((void**)&wql, g_wql);
    cudaGetSymbolAddress((void**)&wkh, g_wkh); cudaGetSymbolAddress((void**)&wkl, g_wkl);
    cudaGetSymbolAddress((void**)&woh, g_woh); cudaGetSymbolAddress((void**)&wol, g_wol);
    cudaGetSymbolAddress((void**)&gqk, g_qk);
    cudaGetSymbolAddress((void**)&gperm, g_perm);

    detect_mask_kernel<<<1, 256>>>((const unsigned int*)mask);
    expand_mask_kernel<<<BATCH / 256, 256>>>(mask);
    compact_kernel<<<1, 1024>>>();

    split_kernel<<<(128 * 256) / 256, 256>>>(Wq, wqh, wql, 128 * 256);
    transpose_split_wk<<<(NHEADS * ADIM * EMB) / 256, 256>>>(Wk);
    split_kernel<<<(256 * 512) / 256, 256>>>(Wout, woh, wol, 256 * 512);
    gather_split_center<<<(BATCH * EMB) / 256, 256>>>(center);

    // q = center_c @ Wq^T : [Bv,128], K=256, N=128 -> bf16 split output
    {
        dim3 grid(1, BATCH / 128);
        gemm_mma<<<grid, 256>>>(ch, cl, EMB, 0, wqh, wql, EMB, 256,
                                nullptr, 0, qh, ql, 128, nullptr, nullptr);
    }
    // qk[h] = q[:, h*64:(h+1)*64] @ WkT[h]^T : [Bv,256], K=64, N=256 -> fp32
    for (int h = 0; h < NHEADS; h++) {
        dim3 grid(2, BATCH / 128);
        gemm_mma<<<grid, 256>>>(qh, ql, 128, h * ADIM,
                                wkh + h * EMB * ADIM, wkl + h * EMB * ADIM, ADIM, 64,
                                gqk + h * 256, 512, nullptr, nullptr, 0,
                                nullptr, nullptr);
    }

    attn_kernel<<<BATCH, 128>>>(neigh, wts, gqk);
    copy_invalid_kernel<<<BATCH * 64 / 256, 256>>>(center, out);

    // out = ctx @ Wout^T + b : [Bv,256], K=512, N=256 -> fp32 scattered via perm
    {
        dim3 grid(2, BATCH / 128);
        gemm_mma<<<grid, 256>>>(cxh, cxl, 512, 0, woh, wol, 512, 512,
                                out, EMB, nullptr, nullptr, 0, bout, gperm);
    }
}

// round 5
// speedup vs baseline: 1.5713x; 1.0810x over previous
#include <cuda_runtime.h>
#include <cuda_bf16.h>
#include <math.h>
#include <stdint.h>

#define BATCH  32768
#define EMB    256
#define ADIM   64
#define NHEADS 2
#define KNEI   16

// ---------------- scratch (device globals; no allocation allowed) ----------------
__device__ __nv_bfloat16 g_ch [BATCH * EMB];     // center gathered, bf16 hi
__device__ __nv_bfloat16 g_cl [BATCH * EMB];     // center gathered, bf16 lo
__device__ __nv_bfloat16 g_qh [BATCH * 128];     // q hi
__device__ __nv_bfloat16 g_ql [BATCH * 128];     // q lo
__device__ float         g_qk [BATCH * 512];     // qk fp32 (compacted)
__device__ __nv_bfloat16 g_cxh[BATCH * 512];     // ctx hi
__device__ __nv_bfloat16 g_cxl[BATCH * 512];     // ctx lo
__device__ __nv_bfloat16 g_wqh[128 * 256], g_wql[128 * 256];
__device__ __nv_bfloat16 g_wkh[NHEADS * 256 * 64], g_wkl[NHEADS * 256 * 64];  // WkT [h][d][a]
__device__ __nv_bfloat16 g_woh[256 * 512], g_wol[256 * 512];
__device__ int g_valid[BATCH];
__device__ int g_perm [BATCH];    // [0,nv): valid rows, [nv,BATCH): invalid rows
__device__ int g_nvalid;
__device__ int g_maskflag;

// ---------------- helpers ----------------
__device__ __forceinline__ uint32_t smem_u32(const void* p) {
    uint32_t a;
    asm("{ .reg .u64 t; cvta.to.shared.u64 t, %1; cvt.u32.u64 %0, t; }" : "=r"(a) : "l"(p));
    return a;
}

#define LDSM4(r0, r1, r2, r3, addr) \
    asm volatile("ldmatrix.sync.aligned.m8n8.x4.shared.b16 {%0,%1,%2,%3}, [%4];" \
                 : "=r"(r0), "=r"(r1), "=r"(r2), "=r"(r3) : "r"(addr))

#define MMA16816(d, a, b0, b1) \
    asm volatile("mma.sync.aligned.m16n8k16.row.col.f32.bf16.bf16.f32 " \
                 "{%0,%1,%2,%3}, {%4,%5,%6,%7}, {%8,%9}, {%0,%1,%2,%3};" \
                 : "+f"((d)[0]), "+f"((d)[1]), "+f"((d)[2]), "+f"((d)[3]) \
                 : "r"((a)[0]), "r"((a)[1]), "r"((a)[2]), "r"((a)[3]), \
                   "r"(b0), "r"(b1))

#define CP16(dst, src) \
    asm volatile("cp.async.cg.shared.global [%0], [%1], 16;" :: "r"(dst), "l"(src) : "memory")
#define CPCOMMIT() asm volatile("cp.async.commit_group;" ::: "memory")
#define CPWAIT1()  asm volatile("cp.async.wait_group 1;" ::: "memory")
#define CPWAIT0()  asm volatile("cp.async.wait_group 0;" ::: "memory")

// ---------------- mask dtype detection + expansion + compaction ----------------
__global__ void detect_mask_kernel(const unsigned int* __restrict__ m) {
    __shared__ int s;
    if (threadIdx.x == 0) s = 0;
    __syncthreads();
    int found = 0;
    for (int i = threadIdx.x; i < 2048; i += blockDim.x)
        if (m[i] > 1u) found = 1;
    if (found) s = 1;
    __syncthreads();
    if (threadIdx.x == 0) g_maskflag = s;
}

__global__ void expand_mask_kernel(const void* __restrict__ m) {
    int i = blockIdx.x * blockDim.x + threadIdx.x;
    if (i >= BATCH) return;
    int v;
    if (g_maskflag) v = (((const unsigned char*)m)[i] != 0);
    else            v = (((const int*)m)[i] != 0);
    g_valid[i] = v;
}

// perm[0..nv) = valid rows (ordered); perm[nv..BATCH) = invalid rows (ordered)
__global__ void compact_kernel() {
    __shared__ int s[1024];
    const int t = threadIdx.x;
    const int base = t * 32;
    int c = 0;
    #pragma unroll 4
    for (int i = 0; i < 32; i++) c += g_valid[base + i];
    s[t] = c;
    __syncthreads();
    for (int off = 1; off < 1024; off <<= 1) {
        int v = (t >= off) ? s[t - off] : 0;
        __syncthreads();
        s[t] += v;
        __syncthreads();
    }
    const int total = s[1023];
    int o  = s[t] - c;                    // exclusive valid prefix
    int oi = total + (base - o);          // invalid destination
    for (int i = 0; i < 32; i++) {
        int b = base + i;
        if (g_valid[b]) g_perm[o++]  = b;
        else            g_perm[oi++] = b;
    }
    if (t == 0) g_nvalid = total;
}

// ---------------- bf16 hi/lo split preps ----------------
__device__ __forceinline__ void split1(float v, __nv_bfloat16* hi, __nv_bfloat16* lo) {
    __nv_bfloat16 h = __float2bfloat16(v);
    *hi = h;
    *lo = __float2bfloat16(v - __bfloat162float(h));
}

// one kernel: split Wq (32768), transpose+split Wk (32768), split Wout (131072)
__global__ void prep_weights(const float* __restrict__ Wq,
                             const float* __restrict__ Wk,
                             const float* __restrict__ Wout) {
    int idx = blockIdx.x * blockDim.x + threadIdx.x;   // 0 .. 196607
    if (idx < 32768) {
        split1(Wq[idx], g_wqh + idx, g_wql + idx);
    } else if (idx < 65536) {
        int j = idx - 32768;
        int h = j / (ADIM * EMB);
        int r = j - h * (ADIM * EMB);
        int a = r / EMB;
        int d = r - a * EMB;
        int o = h * EMB * ADIM + d * ADIM + a;
        split1(Wk[j], g_wkh + o, g_wkl + o);
    } else {
        int j = idx - 65536;
        split1(Wout[j], g_woh + j, g_wol + j);
    }
}

__global__ void gather_split_center(const float* __restrict__ center) {
    int i = blockIdx.x * blockDim.x + threadIdx.x;   // over BATCH*EMB
    int row = i >> 8, d = i & 255;
    if (row >= g_nvalid) return;
    float v = center[(size_t)g_perm[row] * EMB + d];
    split1(v, g_ch + i, g_cl + i);
}

// ---------------- bf16x3 HMMA GEMM, BK=64, cp.async double-buffered ----------------
// Block 128x128, 8 warps (4x2), warp tile 32x64.
// smem per stage: 4 matrices (Ahi,Alo,Bhi,Blo) of 128 x 72 bf16 (144B rows).
#define PADE 72
#define MATB (128 * PADE * 2)        // 18432 bytes per matrix
#define STGB (4 * MATB)              // 73728 bytes per stage
#define SMEM_TOT (2 * STGB)          // 147456

__global__ __launch_bounds__(256) void gemm_mma(
    const __nv_bfloat16* __restrict__ Ahi, const __nv_bfloat16* __restrict__ Alo,
    int lda, int acol,
    const __nv_bfloat16* __restrict__ Bhi, const __nv_bfloat16* __restrict__ Blo,
    int ldb, int Kdim,
    float* __restrict__ Cf, int ldcf,
    __nv_bfloat16* __restrict__ Chi, __nv_bfloat16* __restrict__ Clo, int ldcb,
    const float* __restrict__ bias,
    const int* __restrict__ Cperm)
{
    extern __shared__ __align__(16) char dynsm[];

    const int nvalid = g_nvalid;
    const int m0 = blockIdx.y * 128;
    if (m0 >= nvalid) return;
    const int n0 = blockIdx.x * 128;

    const int t    = threadIdx.x;
    const int wid  = t >> 5;
    const int lane = t & 31;
    const int wm   = wid >> 1;
    const int wn   = wid & 1;

    const uint32_t sbase = smem_u32(dynsm);

    float c[2][8][4];
    #pragma unroll
    for (int mi = 0; mi < 2; mi++)
        #pragma unroll
        for (int nj = 0; nj < 8; nj++)
            #pragma unroll
            for (int r = 0; r < 4; r++) c[mi][nj][r] = 0.f;

    const int la = lane & 15, ga = lane >> 4;
    const int lb = lane & 7,  gb = lane >> 3;
    const uint32_t aoff = (uint32_t)((wm * 32 + la) * 144 + ga * 16);
    const uint32_t boff = (uint32_t)((wn * 64 + lb + (gb >> 1) * 8) * 144 + (gb & 1) * 16);

    const int nStages = Kdim >> 6;

    // per-thread load slots (16 x 16B chunks per stage)
    // idx = i*256+t; mat = idx>>10; rem = idx&1023; row = rem>>3; c8 = rem&7
    auto load_stage = [&](int s, int buf) {
        const int kb = s * 64;
        const uint32_t dstb = sbase + (uint32_t)buf * STGB;
        #pragma unroll
        for (int i = 0; i < 16; i++) {
            int idx = i * 256 + t;
            int mat = idx >> 10;
            int rem = idx & 1023;
            int row = rem >> 3, c8 = rem & 7;
            const __nv_bfloat16* src;
            if (mat == 0)      src = Ahi + (size_t)(m0 + row) * lda + acol + kb + c8 * 8;
            else if (mat == 1) src = Alo + (size_t)(m0 + row) * lda + acol + kb + c8 * 8;
            else if (mat == 2) src = Bhi + (size_t)(n0 + row) * ldb + kb + c8 * 8;
            else               src = Blo + (size_t)(n0 + row) * ldb + kb + c8 * 8;
            uint32_t dst = dstb + (uint32_t)mat * MATB + (uint32_t)(row * 144 + c8 * 16);
            CP16(dst, src);
        }
        CPCOMMIT();
    };

    load_stage(0, 0);

    for (int s = 0; s < nStages; s++) {
        const int buf = s & 1;
        const bool more = (s + 1 < nStages);
        if (more) load_stage(s + 1, buf ^ 1);
        if (more) CPWAIT1(); else CPWAIT0();
        __syncthreads();

        const uint32_t bA = sbase + (uint32_t)buf * STGB;
        const uint32_t bAhi = bA, bAlo = bA + MATB, bBhi = bA + 2 * MATB, bBlo = bA + 3 * MATB;

        #pragma unroll
        for (int kk = 0; kk < 4; kk++) {
            const uint32_t kby = kk * 32;
            uint32_t ah[2][4], al[2][4];
            #pragma unroll
            for (int mi = 0; mi < 2; mi++) {
                uint32_t adr = aoff + (uint32_t)(mi * 16 * 144) + kby;
                LDSM4(ah[mi][0], ah[mi][1], ah[mi][2], ah[mi][3], bAhi + adr);
                LDSM4(al[mi][0], al[mi][1], al[mi][2], al[mi][3], bAlo + adr);
            }
            uint32_t bh[4][4], bl[4][4];
            #pragma unroll
            for (int nj = 0; nj < 4; nj++) {
                uint32_t adr = boff + (uint32_t)(nj * 16 * 144) + kby;
                LDSM4(bh[nj][0], bh[nj][1], bh[nj][2], bh[nj][3], bBhi + adr);
                LDSM4(bl[nj][0], bl[nj][1], bl[nj][2], bl[nj][3], bBlo + adr);
            }
            #pragma unroll
            for (int mi = 0; mi < 2; mi++)
                #pragma unroll
                for (int t8 = 0; t8 < 8; t8++) {
                    const int nj = t8 >> 1, sel = (t8 & 1) * 2;
                    MMA16816(c[mi][t8], ah[mi], bh[nj][sel], bh[nj][sel + 1]);
                    MMA16816(c[mi][t8], al[mi], bh[nj][sel], bh[nj][sel + 1]);
                    MMA16816(c[mi][t8], ah[mi], bl[nj][sel], bl[nj][sel + 1]);
                }
        }
        __syncthreads();
    }

    // ---- epilogue ----
    const int rit  = lane >> 2;
    const int colp = (lane & 3) * 2;
    #pragma unroll
    for (int mi = 0; mi < 2; mi++) {
        #pragma unroll
        for (int half = 0; half < 2; half++) {
            const int gm = m0 + wm * 32 + mi * 16 + half * 8 + rit;
            const bool storeOK = (Cperm == nullptr) || (gm < nvalid);
            if (!storeOK) continue;
            const int crow = Cperm ? Cperm[gm] : gm;
            #pragma unroll
            for (int t8 = 0; t8 < 8; t8++) {
                const int col = n0 + wn * 64 + t8 * 8 + colp;
                float v0 = c[mi][t8][half * 2 + 0];
                float v1 = c[mi][t8][half * 2 + 1];
                if (Cf) {
                    if (bias) { v0 += bias[col]; v1 += bias[col + 1]; }
                    *reinterpret_cast<float2*>(Cf + (size_t)crow * ldcf + col) =
                        make_float2(v0, v1);
                } else {
                    __nv_bfloat16 h0 = __float2bfloat16(v0);
                    __nv_bfloat16 h1 = __float2bfloat16(v1);
                    __nv_bfloat16 l0 = __float2bfloat16(v0 - __bfloat162float(h0));
                    __nv_bfloat16 l1 = __float2bfloat16(v1 - __bfloat162float(h1));
                    *reinterpret_cast<__nv_bfloat162*>(Chi + (size_t)gm * ldcb + col) =
                        __nv_bfloat162(h0, h1);
                    *reinterpret_cast<__nv_bfloat162*>(Clo + (size_t)gm * ldcb + col) =
                        __nv_bfloat162(l0, l1);
                }
            }
        }
    }
}

// ---------------- fused attention (valid) + passthrough copy (invalid) ----------------
__global__ __launch_bounds__(128) void attn_kernel(
    const float* __restrict__ center,
    const float* __restrict__ neigh,
    const float* __restrict__ wts,
    const float* __restrict__ qk,
    float* __restrict__ out)
{
    const int i = blockIdx.x;
    const int t = threadIdx.x;
    const int b = g_perm[i];

    if (i >= g_nvalid) {
        // invalid row: out = center
        const float4* src = reinterpret_cast<const float4*>(center + (long)b * EMB);
        float4*       dst = reinterpret_cast<float4*>(out + (long)b * EMB);
        if (t < 64) dst[t] = src[t];
        return;
    }

    __shared__ float sn[KNEI * EMB];
    __shared__ float sq[512];
    __shared__ float sscore[32];
    __shared__ float sattn[32];

    const float4* np = reinterpret_cast<const float4*>(neigh + (long)b * KNEI * EMB);
    float4* snp = reinterpret_cast<float4*>(sn);
    #pragma unroll
    for (int r = 0; r < 8; r++) snp[t + r * 128] = np[t + r * 128];
    reinterpret_cast<float4*>(sq)[t] =
        reinterpret_cast<const float4*>(qk + (long)i * 512)[t];
    __syncthreads();

    {
        const int g = t >> 2, sub = t & 3;
        const int h = g >> 4, j = g & 15;
        const float* qh = sq + h * EMB;
        const float* nj = sn + j * EMB;
        float p = 0.f;
        #pragma unroll 8
        for (int d = sub; d < EMB; d += 4) p += qh[d] * nj[d];
        p += __shfl_xor_sync(0xffffffffu, p, 1);
        p += __shfl_xor_sync(0xffffffffu, p, 2);
        if (sub == 0) sscore[g] = p * 0.125f;
    }
    __syncthreads();

    {
        const int wid = t >> 5, lane = t & 31;
        if (wid < NHEADS && lane < KNEI) {
            float s = sscore[wid * KNEI + lane];
            float m = s;
            #pragma unroll
            for (int o = 8; o > 0; o >>= 1) m = fmaxf(m, __shfl_xor_sync(0xffffu, m, o));
            float e = expf(s - m);
            float se = e;
            #pragma unroll
            for (int o = 8; o > 0; o >>= 1) se += __shfl_xor_sync(0xffffu, se, o);
            float a = (e / se) * wts[b * KNEI + lane];
            float sa = a;
            #pragma unroll
            for (int o = 8; o > 0; o >>= 1) sa += __shfl_xor_sync(0xffffu, sa, o);
            sattn[wid * KNEI + lane] = a / (sa + 1e-8f);
        }
    }
    __syncthreads();

    #pragma unroll
    for (int r = 0; r < 4; r++) {
        const int idx = r * 128 + t;
        const int d = idx & 255, h = idx >> 8;
        float acc = 0.f;
        #pragma unroll
        for (int j = 0; j < KNEI; j++) acc += sattn[h * KNEI + j] * sn[j * EMB + d];
        __nv_bfloat16 hi = __float2bfloat16(acc);
        g_cxh[(size_t)i * 512 + idx] = hi;
        g_cxl[(size_t)i * 512 + idx] = __float2bfloat16(acc - __bfloat162float(hi));
    }
}

// ---------------- launch ----------------
extern "C" void kernel_launch(void* const* d_in, const int* in_sizes, int n_in,
                              void* d_out, int out_size)
{
    const float* center = (const float*)d_in[0];
    const float* neigh  = (const float*)d_in[1];
    const float* wts    = (const float*)d_in[2];
    const void*  mask   = d_in[3];
    const float* Wq     = (const float*)d_in[4];   // [128, 256]
    const float* Wk     = (const float*)d_in[5];   // [2, 64, 256]
    const float* Wout   = (const float*)d_in[6];   // [256, 512]
    const float* bout   = (const float*)d_in[7];
    float* out = (float*)d_out;

    __nv_bfloat16 *ch, *cl, *qh, *ql, *cxh, *cxl, *wqh, *wql, *wkh, *wkl, *woh, *wol;
    float *gqk;
    int *gperm;
    cudaGetSymbolAddress((void**)&ch,  g_ch);  cudaGetSymbolAddress((void**)&cl,  g_cl);
    cudaGetSymbolAddress((void**)&qh,  g_qh);  cudaGetSymbolAddress((void**)&ql,  g_ql);
    cudaGetSymbolAddress((void**)&cxh, g_cxh); cudaGetSymbolAddress((void**)&cxl, g_cxl);
    cudaGetSymbolAddress((void**)&wqh, g_wqh); cudaGetSymbolAddress((void**)&wql, g_wql);
    cudaGetSymbolAddress((void**)&wkh, g_wkh); cudaGetSymbolAddress((void**)&wkl, g_wkl);
    cudaGetSymbolAddress((void**)&woh, g_woh); cudaGetSymbolAddress((void**)&wol, g_wol);
    cudaGetSymbolAddress((void**)&gqk, g_qk);
    cudaGetSymbolAddress((void**)&gperm, g_perm);

    cudaFuncSetAttribute(gemm_mma, cudaFuncAttributeMaxDynamicSharedMemorySize, SMEM_TOT);

    detect_mask_kernel<<<1, 256>>>((const unsigned int*)mask);
    expand_mask_kernel<<<BATCH / 256, 256>>>(mask);
    compact_kernel<<<1, 1024>>>();
    prep_weights<<<196608 / 256, 256>>>(Wq, Wk, Wout);
    gather_split_center<<<(BATCH * EMB) / 256, 256>>>(center);

    // q = center_c @ Wq^T : [Bv,128], K=256, N=128 -> bf16 split output
    {
        dim3 grid(1, BATCH / 128);
        gemm_mma<<<grid, 256, SMEM_TOT>>>(ch, cl, EMB, 0, wqh, wql, EMB, 256,
                                          nullptr, 0, qh, ql, 128, nullptr, nullptr);
    }
    // qk[h] = q[:, h*64:(h+1)*64] @ WkT[h]^T : [Bv,256], K=64, N=256 -> fp32
    for (int h = 0; h < NHEADS; h++) {
        dim3 grid(2, BATCH / 128);
        gemm_mma<<<grid, 256, SMEM_TOT>>>(qh, ql, 128, h * ADIM,
                                          wkh + h * EMB * ADIM, wkl + h * EMB * ADIM, ADIM, 64,
                                          gqk + h * 256, 512, nullptr, nullptr, 0,
                                          nullptr, nullptr);
    }

    // attention on valid rows + passthrough on invalid rows
    attn_kernel<<<BATCH, 128>>>(center, neigh, wts, gqk, out);

    // out = ctx @ Wout^T + b : [Bv,256], K=512, N=256 -> fp32 scattered via perm
    {
        dim3 grid(2, BATCH / 128);
        gemm_mma<<<grid, 256, SMEM_TOT>>>(cxh, cxl, 512, 0, woh, wol, 512, 512,
                                          out, EMB, nullptr, nullptr, 0, bout, gperm);
    }
}